// round 2
// baseline (speedup 1.0000x reference)
#include <cuda_runtime.h>

#define N_ROWS 8192
#define H_DIM  512
#define M_FEAT 4096
#define K_TOP  64

// ---------------- scratch (static device globals: allocation-free) ----------
__device__ float g_logits[(size_t)N_ROWS * M_FEAT];   // 128 MB, relu'd logits
__device__ float g_decT[(size_t)M_FEAT * H_DIM];      // 8 MB, decoder [M,H]
__device__ int   g_top_idx[N_ROWS * K_TOP];
__device__ float g_top_val[N_ROWS * K_TOP];
__device__ float g_row_recon[N_ROWS];
__device__ float g_row_sparse[N_ROWS];

// ---------------- transpose dec [H, M] -> decT [M, H] -----------------------
__global__ void transpose_dec(const float* __restrict__ dec)
{
    __shared__ float t[32][33];
    const int bx = blockIdx.x;            // M / 32
    const int by = blockIdx.y;            // H / 32
    const int tx = threadIdx.x, ty = threadIdx.y;   // 32 x 8
#pragma unroll
    for (int j = 0; j < 4; ++j) {
        int h = by * 32 + ty + j * 8;
        int m = bx * 32 + tx;
        t[ty + j * 8][tx] = dec[(size_t)h * M_FEAT + m];
    }
    __syncthreads();
#pragma unroll
    for (int j = 0; j < 4; ++j) {
        int m = bx * 32 + ty + j * 8;
        int h = by * 32 + tx;
        g_decT[(size_t)m * H_DIM + h] = t[tx][ty + j * 8];
    }
}

// ---------------- encoder GEMM: relu((x - bp) @ enc^T + be) -----------------
// A = x [N, 512], B = enc [M, 512], C = g_logits [N, M]. NT GEMM (K-major both).
// 128x128 tile, BK=16, 256 threads, 8x8 per thread, global prefetch.
__global__ __launch_bounds__(256, 2)
void gemm_enc_relu(const float* __restrict__ x, const float* __restrict__ enc,
                   const float* __restrict__ bias_pre, const float* __restrict__ bias_enc)
{
    __shared__ float As[16][128];
    __shared__ float Bs[16][128];

    const int tid = threadIdx.x;
    const int tx = tid & 15;
    const int ty = tid >> 4;
    const int nBase = blockIdx.y * 128;
    const int mBase = blockIdx.x * 128;

    // vectorized tile load mapping: 512 float4 per tile, 2 per thread
    const int vrow0 = tid >> 2;                 // 0..63
    const int vc0   = (tid & 3) << 2;           // 0,4,8,12
    const int vrow1 = vrow0 + 64;

    const float* Ap0 = x   + (size_t)(nBase + vrow0) * H_DIM + vc0;
    const float* Ap1 = x   + (size_t)(nBase + vrow1) * H_DIM + vc0;
    const float* Bp0 = enc + (size_t)(mBase + vrow0) * H_DIM + vc0;
    const float* Bp1 = enc + (size_t)(mBase + vrow1) * H_DIM + vc0;

    float4 ra0 = *(const float4*)(Ap0);
    float4 ra1 = *(const float4*)(Ap1);
    float4 rb0 = *(const float4*)(Bp0);
    float4 rb1 = *(const float4*)(Bp1);

    float acc[8][8];
#pragma unroll
    for (int i = 0; i < 8; ++i)
#pragma unroll
        for (int j = 0; j < 8; ++j) acc[i][j] = 0.f;

#pragma unroll 1
    for (int kt = 0; kt < 32; ++kt) {
        const int k0 = kt * 16;
        const float4 bp = *(const float4*)(bias_pre + k0 + vc0);

        As[vc0 + 0][vrow0] = ra0.x - bp.x;
        As[vc0 + 1][vrow0] = ra0.y - bp.y;
        As[vc0 + 2][vrow0] = ra0.z - bp.z;
        As[vc0 + 3][vrow0] = ra0.w - bp.w;
        As[vc0 + 0][vrow1] = ra1.x - bp.x;
        As[vc0 + 1][vrow1] = ra1.y - bp.y;
        As[vc0 + 2][vrow1] = ra1.z - bp.z;
        As[vc0 + 3][vrow1] = ra1.w - bp.w;
        Bs[vc0 + 0][vrow0] = rb0.x;
        Bs[vc0 + 1][vrow0] = rb0.y;
        Bs[vc0 + 2][vrow0] = rb0.z;
        Bs[vc0 + 3][vrow0] = rb0.w;
        Bs[vc0 + 0][vrow1] = rb1.x;
        Bs[vc0 + 1][vrow1] = rb1.y;
        Bs[vc0 + 2][vrow1] = rb1.z;
        Bs[vc0 + 3][vrow1] = rb1.w;
        __syncthreads();

        if (kt < 31) {   // prefetch next K tile
            ra0 = *(const float4*)(Ap0 + k0 + 16);
            ra1 = *(const float4*)(Ap1 + k0 + 16);
            rb0 = *(const float4*)(Bp0 + k0 + 16);
            rb1 = *(const float4*)(Bp1 + k0 + 16);
        }

#pragma unroll
        for (int kk = 0; kk < 16; ++kk) {
            float4 a0 = *(const float4*)&As[kk][ty * 8];
            float4 a1 = *(const float4*)&As[kk][ty * 8 + 4];
            float4 b0 = *(const float4*)&Bs[kk][tx * 8];
            float4 b1 = *(const float4*)&Bs[kk][tx * 8 + 4];
            float av[8] = {a0.x, a0.y, a0.z, a0.w, a1.x, a1.y, a1.z, a1.w};
            float bv[8] = {b0.x, b0.y, b0.z, b0.w, b1.x, b1.y, b1.z, b1.w};
#pragma unroll
            for (int i = 0; i < 8; ++i)
#pragma unroll
                for (int j = 0; j < 8; ++j)
                    acc[i][j] += av[i] * bv[j];
        }
        __syncthreads();
    }

    // epilogue: + bias_enc, relu, store
    const float4 be0 = *(const float4*)(bias_enc + mBase + tx * 8);
    const float4 be1 = *(const float4*)(bias_enc + mBase + tx * 8 + 4);
#pragma unroll
    for (int i = 0; i < 8; ++i) {
        const int row = nBase + ty * 8 + i;
        float* out = g_logits + (size_t)row * M_FEAT + mBase + tx * 8;
        float4 o0, o1;
        o0.x = fmaxf(acc[i][0] + be0.x, 0.f);
        o0.y = fmaxf(acc[i][1] + be0.y, 0.f);
        o0.z = fmaxf(acc[i][2] + be0.z, 0.f);
        o0.w = fmaxf(acc[i][3] + be0.w, 0.f);
        o1.x = fmaxf(acc[i][4] + be1.x, 0.f);
        o1.y = fmaxf(acc[i][5] + be1.y, 0.f);
        o1.z = fmaxf(acc[i][6] + be1.z, 0.f);
        o1.w = fmaxf(acc[i][7] + be1.w, 0.f);
        *(float4*)out       = o0;
        *(float4*)(out + 4) = o1;
    }
}

// ---------------- exact per-row top-64 via 32-bit radix select ---------------
// Values are relu'd (>= 0) so float bits are monotonic as uint. Deterministic:
// threshold is exact; collection uses index-ordered block scans (no float atomics).
__global__ __launch_bounds__(256)
void topk_kernel()
{
    __shared__ __align__(16) float s_row[M_FEAT];
    __shared__ int s_hist[256];
    __shared__ int s_scan[256];
    __shared__ int s_tidx[K_TOP];
    __shared__ float s_tval[K_TOP];
    __shared__ unsigned s_prefix;
    __shared__ int s_krem;

    const int tid = threadIdx.x;
    const int row = blockIdx.x;
    const float4* src = (const float4*)(g_logits + (size_t)row * M_FEAT);
#pragma unroll
    for (int i = 0; i < 4; ++i)
        ((float4*)s_row)[tid + i * 256] = src[tid + i * 256];
    if (tid == 0) { s_prefix = 0u; s_krem = K_TOP; }
    __syncthreads();

    const int base = tid * 16;

    // 4 radix passes, MSB byte first -> exact 32-bit threshold of 64th largest
    for (int p = 3; p >= 0; --p) {
        s_hist[tid] = 0;
        __syncthreads();
        const unsigned pmask = (p == 3) ? 0u : (0xFFFFFFFFu << ((p + 1) * 8));
        const unsigned pref = s_prefix;
#pragma unroll
        for (int i = 0; i < 16; ++i) {
            unsigned b = __float_as_uint(s_row[base + i]);
            if ((b & pmask) == pref) atomicAdd(&s_hist[(b >> (p * 8)) & 255], 1);
        }
        __syncthreads();
        if (tid == 0) {
            int krem = s_krem, cum = 0, bin = 255;
            for (; bin > 0; --bin) {
                int h = s_hist[bin];
                if (cum + h >= krem) break;
                cum += h;
            }
            s_prefix = pref | ((unsigned)bin << (p * 8));
            s_krem = krem - cum;
        }
        __syncthreads();
    }

    const unsigned T = s_prefix;

    int c_gt = 0, c_eq = 0;
#pragma unroll
    for (int i = 0; i < 16; ++i) {
        unsigned b = __float_as_uint(s_row[base + i]);
        c_gt += (b > T);
        c_eq += (b == T);
    }

    // block inclusive scan (Hillis-Steele) for > T
    s_scan[tid] = c_gt;
    __syncthreads();
    for (int o = 1; o < 256; o <<= 1) {
        int v = (tid >= o) ? s_scan[tid - o] : 0;
        __syncthreads();
        s_scan[tid] += v;
        __syncthreads();
    }
    const int off_gt = s_scan[tid] - c_gt;
    const int tot_gt = s_scan[255];
    __syncthreads();

    // scan for == T (ties filled lowest-index-first, deterministically)
    s_scan[tid] = c_eq;
    __syncthreads();
    for (int o = 1; o < 256; o <<= 1) {
        int v = (tid >= o) ? s_scan[tid - o] : 0;
        __syncthreads();
        s_scan[tid] += v;
        __syncthreads();
    }
    const int off_eq = s_scan[tid] - c_eq;
    __syncthreads();

    int p_gt = off_gt;
    int p_eq = tot_gt + off_eq;
#pragma unroll
    for (int i = 0; i < 16; ++i) {
        float v = s_row[base + i];
        unsigned b = __float_as_uint(v);
        if (b > T) {
            s_tidx[p_gt] = base + i; s_tval[p_gt] = v; ++p_gt;
        } else if (b == T && p_eq < K_TOP) {
            s_tidx[p_eq] = base + i; s_tval[p_eq] = v; ++p_eq;
        }
    }
    __syncthreads();

    if (tid < K_TOP) {
        g_top_idx[row * K_TOP + tid] = s_tidx[tid];
        g_top_val[row * K_TOP + tid] = s_tval[tid];
    }
    if (tid == 0) {   // sequential fixed-order sum: deterministic
        float s = 0.f;
        for (int i = 0; i < K_TOP; ++i) s += s_tval[i];
        g_row_sparse[row] = s;
    }
}

// ---------------- sparse decode + per-row squared residual ------------------
__global__ __launch_bounds__(128)
void decode_recon(const float* __restrict__ x)
{
    __shared__ int s_idx[K_TOP];
    __shared__ float s_val[K_TOP];
    __shared__ float s_red[128];
    const int tid = threadIdx.x;
    const int row = blockIdx.x;

    if (tid < K_TOP) {
        s_idx[tid] = g_top_idx[row * K_TOP + tid];
        s_val[tid] = g_top_val[row * K_TOP + tid];
    }
    __syncthreads();

    float4 acc = make_float4(0.f, 0.f, 0.f, 0.f);
#pragma unroll 8
    for (int j = 0; j < K_TOP; ++j) {
        const float v = s_val[j];
        const float4 d = ((const float4*)(g_decT + (size_t)s_idx[j] * H_DIM))[tid];
        acc.x += v * d.x; acc.y += v * d.y; acc.z += v * d.z; acc.w += v * d.w;
    }
    const float4 xs = ((const float4*)(x + (size_t)row * H_DIM))[tid];
    const float dx = acc.x - xs.x;
    const float dy = acc.y - xs.y;
    const float dz = acc.z - xs.z;
    const float dw = acc.w - xs.w;
    s_red[tid] = dx * dx + dy * dy + dz * dz + dw * dw;
    __syncthreads();
    for (int o = 64; o > 0; o >>= 1) {
        if (tid < o) s_red[tid] += s_red[tid + o];
        __syncthreads();
    }
    if (tid == 0) g_row_recon[row] = s_red[0];
}

// ---------------- final deterministic reduction ------------------------------
__global__ __launch_bounds__(1024)
void final_reduce(float* __restrict__ out)
{
    __shared__ float s_a[1024];
    __shared__ float s_b[1024];
    const int tid = threadIdx.x;
    float ra = 0.f, rb = 0.f;
#pragma unroll
    for (int i = 0; i < 8; ++i) {
        ra += g_row_recon[tid * 8 + i];
        rb += g_row_sparse[tid * 8 + i];
    }
    s_a[tid] = ra; s_b[tid] = rb;
    __syncthreads();
    for (int o = 512; o > 0; o >>= 1) {
        if (tid < o) { s_a[tid] += s_a[tid + o]; s_b[tid] += s_b[tid + o]; }
        __syncthreads();
    }
    if (tid == 0) {
        const float recon  = s_a[0] / (float)(N_ROWS * H_DIM);
        const float sparse = s_b[0] / (float)(N_ROWS * M_FEAT);
        out[0] = recon + 1e-3f * sparse;
    }
}

// ---------------- launch -----------------------------------------------------
extern "C" void kernel_launch(void* const* d_in, const int* in_sizes, int n_in,
                              void* d_out, int out_size)
{
    const float* zL       = (const float*)d_in[0];
    const float* enc      = (const float*)d_in[1];
    const float* dec      = (const float*)d_in[2];
    const float* bias_pre = (const float*)d_in[3];
    const float* bias_enc = (const float*)d_in[4];

    transpose_dec<<<dim3(M_FEAT / 32, H_DIM / 32), dim3(32, 8)>>>(dec);
    gemm_enc_relu<<<dim3(M_FEAT / 128, N_ROWS / 128), 256>>>(zL, enc, bias_pre, bias_enc);
    topk_kernel<<<N_ROWS, 256>>>();
    decode_recon<<<N_ROWS, 128>>>(zL);
    final_reduce<<<1, 1024>>>((float*)d_out);
}

// round 7
// speedup vs baseline: 2.0834x; 2.0834x over previous
#include <cuda_runtime.h>
#include <cstdint>

#define N_ROWS 8192
#define H_DIM  512
#define M_FEAT 4096
#define K_TOP  64

// GEMM tiling: CTA 128(rows) x 128(features), BK=32, 3-stage cp.async pipeline
#define BK 32
#define NITER (H_DIM / BK)            // 16
#define STAGES 3
#define STAGE_BYTES (2 * 128 * BK * 4)  // A tile 16KB + B tile 16KB = 32KB
#define GEMM_SMEM (STAGES * STAGE_BYTES)

// ---------------- scratch (static device globals: allocation-free) ----------
__device__ float g_logits[(size_t)N_ROWS * M_FEAT];   // 128 MB
__device__ float g_decT[(size_t)M_FEAT * H_DIM];      // 8 MB
__device__ float g_xr[(size_t)N_ROWS * H_DIM];        // tf32-rounded x
__device__ float g_er[(size_t)M_FEAT * H_DIM];        // tf32-rounded enc
__device__ float g_coff[M_FEAT];                      // bias_enc - bias_pre@enc^T
__device__ int   g_top_idx[N_ROWS * K_TOP];
__device__ float g_top_val[N_ROWS * K_TOP];
__device__ float g_row_recon[N_ROWS];
__device__ float g_row_sparse[N_ROWS];

// ---------------- PTX helpers (all sm_80-era, no arch-suffix features) ------
__device__ __forceinline__ uint32_t smem_u32(const void* p) {
    uint32_t a;
    asm("{ .reg .u64 t; cvta.to.shared.u64 t, %1; cvt.u32.u64 %0, t; }" : "=r"(a) : "l"(p));
    return a;
}
#define CP_ASYNC16(dst, src) \
    asm volatile("cp.async.cg.shared.global [%0], [%1], 16;" :: "r"(dst), "l"(src))
#define CP_COMMIT() asm volatile("cp.async.commit_group;" ::: "memory")
#define CP_WAIT2()  asm volatile("cp.async.wait_group 2;" ::: "memory")

#define LDMATRIX_X4(r0, r1, r2, r3, a)                                     \
    asm volatile("ldmatrix.sync.aligned.m8n8.x4.shared.b16 {%0,%1,%2,%3}, [%4];" \
        : "=r"(r0), "=r"(r1), "=r"(r2), "=r"(r3) : "r"(a))

#define MMA_TF32(d, a, b0, b1)                                             \
    asm volatile("mma.sync.aligned.m16n8k8.row.col.f32.tf32.tf32.f32 "     \
        "{%0,%1,%2,%3}, {%4,%5,%6,%7}, {%8,%9}, {%0,%1,%2,%3};"            \
        : "+f"((d)[0]), "+f"((d)[1]), "+f"((d)[2]), "+f"((d)[3])           \
        : "r"((a)[0]), "r"((a)[1]), "r"((a)[2]), "r"((a)[3]),              \
          "r"(b0), "r"(b1))

// ---------------- preprocessing ---------------------------------------------
__global__ void round_tf32(const float* __restrict__ in, float* __restrict__ out)
{
    const int i = blockIdx.x * blockDim.x + threadIdx.x;
    float4 v = ((const float4*)in)[i];
    float4 o;
    asm("cvt.rna.tf32.f32 %0, %1;" : "=f"(o.x) : "f"(v.x));
    asm("cvt.rna.tf32.f32 %0, %1;" : "=f"(o.y) : "f"(v.y));
    asm("cvt.rna.tf32.f32 %0, %1;" : "=f"(o.z) : "f"(v.z));
    asm("cvt.rna.tf32.f32 %0, %1;" : "=f"(o.w) : "f"(v.w));
    ((float4*)out)[i] = o;
}

__global__ void coff_kernel(const float* __restrict__ enc,
                            const float* __restrict__ bias_pre,
                            const float* __restrict__ bias_enc)
{
    const int wid = threadIdx.x >> 5, lane = threadIdx.x & 31;
    const int f = blockIdx.x * 8 + wid;
    float s = 0.f;
#pragma unroll
    for (int i = 0; i < 16; ++i) {
        const int k = lane + i * 32;
        s = fmaf(enc[(size_t)f * H_DIM + k], bias_pre[k], s);
    }
#pragma unroll
    for (int o = 16; o > 0; o >>= 1) s += __shfl_down_sync(0xffffffffu, s, o);
    if (lane == 0) g_coff[f] = bias_enc[f] - s;
}

// ---------------- transpose dec [H, M] -> decT [M, H] -----------------------
__global__ void transpose_dec(const float* __restrict__ dec)
{
    __shared__ float t[32][33];
    const int bx = blockIdx.x, by = blockIdx.y;
    const int tx = threadIdx.x, ty = threadIdx.y;
#pragma unroll
    for (int j = 0; j < 4; ++j)
        t[ty + j * 8][tx] = dec[(size_t)(by * 32 + ty + j * 8) * M_FEAT + bx * 32 + tx];
    __syncthreads();
#pragma unroll
    for (int j = 0; j < 4; ++j)
        g_decT[(size_t)(bx * 32 + ty + j * 8) * H_DIM + by * 32 + tx] = t[tx][ty + j * 8];
}

// ---------------- tf32 mma.sync GEMM + bias + relu ---------------------------
// logits[i, j] = relu(sum_k xr[i,k]*er[j,k] + coff[j])
// NT GEMM: both operands K-major, XOR-8 swizzled smem, ldmatrix fragment loads.
__global__ __launch_bounds__(256)
void gemm_mma(const float* __restrict__ xr, const float* __restrict__ er)
{
    extern __shared__ __align__(1024) char smem[];
    const uint32_t smem_b = smem_u32(smem);
    const int tid = threadIdx.x;
    const int lane = tid & 31, warp = tid >> 5;
    const int warp_m = warp & 1;        // 2 warps along rows -> 64 rows each
    const int warp_n = warp >> 1;       // 4 warps along features -> 32 each
    const int nBase = blockIdx.y * 128; // sample rows
    const int mBase = blockIdx.x * 128; // features

    // ---- cp.async per-thread slots (same pattern for A and B regions) ----
    uint32_t offq[4];
    const float* pA[4];
    const float* pB[4];
#pragma unroll
    for (int q = 0; q < 4; ++q) {
        const int v = tid + q * 256;          // 0..1023 = 128 rows x 8 chunks
        const int row = v >> 3, c = v & 7;
        offq[q] = (uint32_t)(row * 128 + ((c ^ (row & 7)) << 4));
        pA[q] = xr + (size_t)(nBase + row) * H_DIM + c * 4;
        pB[q] = er + (size_t)(mBase + row) * H_DIM + c * 4;
    }

    // ---- ldmatrix per-lane address constants ----
    const int qd = lane >> 3, r = lane & 7;
    // A: matrices [rows+0 k0-3][rows+8 k0-3][rows+0 k4-7][rows+8 k4-7]
    const int rowA = warp_m * 64 + ((qd & 1) << 3) + r;
    const int qhA = qd >> 1;
    const uint32_t baseA = (uint32_t)(rowA * 128);
    const int swA = rowA & 7;
    // B: matrices [feat+0 k0-3][feat+0 k4-7][feat+8 k0-3][feat+8 k4-7]
    const int rowB = warp_n * 32 + ((qd >> 1) << 3) + r;
    const int qbB = qd & 1;
    const uint32_t baseB = (uint32_t)(128 * BK * 4 + rowB * 128);
    const int swB = rowB & 7;

    float acc[4][4][4];
#pragma unroll
    for (int mt = 0; mt < 4; ++mt)
#pragma unroll
        for (int nt = 0; nt < 4; ++nt)
#pragma unroll
            for (int e = 0; e < 4; ++e) acc[mt][nt][e] = 0.f;

    // ---- prologue: stages for iters 0,1 ----
#pragma unroll
    for (int i = 0; i < 2; ++i) {
        const uint32_t st = smem_b + i * STAGE_BYTES;
        const int k0 = i * BK;
#pragma unroll
        for (int q = 0; q < 4; ++q) {
            CP_ASYNC16(st + offq[q], pA[q] + k0);
            CP_ASYNC16(st + 128 * BK * 4 + offq[q], pB[q] + k0);
        }
        CP_COMMIT();
    }

#pragma unroll 1
    for (int i = 0; i < NITER; ++i) {
        const int il = i + 2;
        if (il < NITER) {
            const uint32_t st = smem_b + (il % STAGES) * STAGE_BYTES;
            const int k0 = il * BK;
#pragma unroll
            for (int q = 0; q < 4; ++q) {
                CP_ASYNC16(st + offq[q], pA[q] + k0);
                CP_ASYNC16(st + 128 * BK * 4 + offq[q], pB[q] + k0);
            }
        }
        CP_COMMIT();
        CP_WAIT2();                 // iter i's stage fully landed
        __syncthreads();

        const uint32_t st = smem_b + (i % STAGES) * STAGE_BYTES;
#pragma unroll
        for (int ks = 0; ks < 4; ++ks) {
            uint32_t a[4][4];
#pragma unroll
            for (int mt = 0; mt < 4; ++mt) {
                const uint32_t ad = st + baseA + mt * 2048
                                  + (uint32_t)((((ks * 2) | qhA) ^ swA) << 4);
                LDMATRIX_X4(a[mt][0], a[mt][1], a[mt][2], a[mt][3], ad);
            }
            uint32_t b[2][4];
#pragma unroll
            for (int p = 0; p < 2; ++p) {
                const uint32_t bd = st + baseB + p * 2048
                                  + (uint32_t)((((ks * 2) | qbB) ^ swB) << 4);
                LDMATRIX_X4(b[p][0], b[p][1], b[p][2], b[p][3], bd);
            }
#pragma unroll
            for (int mt = 0; mt < 4; ++mt)
#pragma unroll
                for (int nt = 0; nt < 4; ++nt)
                    MMA_TF32(acc[mt][nt], a[mt],
                             b[nt >> 1][(nt & 1) * 2], b[nt >> 1][(nt & 1) * 2 + 1]);
        }
        __syncthreads();            // all warps done with stage i%3 before reuse
    }

    // ---- epilogue: + coff, relu, store ----
#pragma unroll
    for (int mt = 0; mt < 4; ++mt) {
#pragma unroll
        for (int nt = 0; nt < 4; ++nt) {
            const int row0 = nBase + warp_m * 64 + mt * 16 + (lane >> 2);
            const int col  = mBase + warp_n * 32 + nt * 8 + (lane & 3) * 2;
            const float2 cb = *(const float2*)(g_coff + col);
            float2 o0, o1;
            o0.x = fmaxf(acc[mt][nt][0] + cb.x, 0.f);
            o0.y = fmaxf(acc[mt][nt][1] + cb.y, 0.f);
            o1.x = fmaxf(acc[mt][nt][2] + cb.x, 0.f);
            o1.y = fmaxf(acc[mt][nt][3] + cb.y, 0.f);
            *(float2*)(g_logits + (size_t)row0 * M_FEAT + col)       = o0;
            *(float2*)(g_logits + (size_t)(row0 + 8) * M_FEAT + col) = o1;
        }
    }
}

// ---------------- exact per-row top-64, parallel radix select ----------------
__global__ __launch_bounds__(256)
void topk_kernel()
{
    __shared__ __align__(16) float s_row[M_FEAT];
    __shared__ int s_hist[256];
    __shared__ int s_wsum[8];
    __shared__ int s_tidx[K_TOP];
    __shared__ float s_tval[K_TOP];
    __shared__ unsigned s_prefix;
    __shared__ int s_krem;

    const int tid = threadIdx.x;
    const int lane = tid & 31, wid = tid >> 5;
    const int row = blockIdx.x;
    const float4* src = (const float4*)(g_logits + (size_t)row * M_FEAT);
#pragma unroll
    for (int i = 0; i < 4; ++i)
        ((float4*)s_row)[tid + i * 256] = src[tid + i * 256];
    if (tid == 0) { s_prefix = 0u; s_krem = K_TOP; }
    __syncthreads();

    const int base = tid * 16;

#pragma unroll 1
    for (int p = 3; p >= 0; --p) {
        const unsigned pref = s_prefix;
        const int krem = s_krem;
        s_hist[tid] = 0;
        __syncthreads();
        const unsigned pmask = (p == 3) ? 0u : (0xFFFFFFFFu << ((p + 1) * 8));
        const int shift = p * 8;
#pragma unroll
        for (int i = 0; i < 16; ++i) {
            unsigned b = __float_as_uint(s_row[base + i]);
            if ((b & pmask) == pref) atomicAdd(&s_hist[(b >> shift) & 255], 1);
        }
        __syncthreads();
        // parallel suffix count over bins: thread handles bin = 255 - tid
        const int bin = 255 - tid;
        const int h = s_hist[bin];
        int x = h;
#pragma unroll
        for (int o = 1; o < 32; o <<= 1) {
            int y = __shfl_up_sync(0xffffffffu, x, o);
            if (lane >= o) x += y;
        }
        if (lane == 31) s_wsum[wid] = x;
        __syncthreads();
        int off = 0;
#pragma unroll
        for (int w = 0; w < 8; ++w) off += (w < wid) ? s_wsum[w] : 0;
        const int cnt_ge = x + off;     // count of values with byte-bin >= bin
        if (cnt_ge >= krem && (cnt_ge - h) < krem) {   // exactly one thread
            s_prefix = pref | ((unsigned)bin << shift);
            s_krem = krem - (cnt_ge - h);
        }
        __syncthreads();
    }

    const unsigned T = s_prefix;

    int c_gt = 0, c_eq = 0;
#pragma unroll
    for (int i = 0; i < 16; ++i) {
        unsigned b = __float_as_uint(s_row[base + i]);
        c_gt += (b > T);
        c_eq += (b == T);
    }
    const int packed = c_gt | (c_eq << 16);
    int x = packed;
#pragma unroll
    for (int o = 1; o < 32; o <<= 1) {
        int y = __shfl_up_sync(0xffffffffu, x, o);
        if (lane >= o) x += y;
    }
    if (lane == 31) s_wsum[wid] = x;
    __syncthreads();
    int off = 0, tot = 0;
#pragma unroll
    for (int w = 0; w < 8; ++w) {
        const int v = s_wsum[w];
        if (w < wid) off += v;
        tot += v;
    }
    const int incl = x + off;
    const int excl = incl - packed;
    const int tot_gt = tot & 0xffff;
    int p_gt = excl & 0xffff;
    int p_eq = tot_gt + (excl >> 16);

#pragma unroll
    for (int i = 0; i < 16; ++i) {
        const float v = s_row[base + i];
        const unsigned b = __float_as_uint(v);
        if (b > T) {
            s_tidx[p_gt] = base + i; s_tval[p_gt] = v; ++p_gt;
        } else if (b == T && p_eq < K_TOP) {
            s_tidx[p_eq] = base + i; s_tval[p_eq] = v; ++p_eq;
        }
    }
    __syncthreads();

    if (tid < K_TOP) {
        g_top_idx[row * K_TOP + tid] = s_tidx[tid];
        g_top_val[row * K_TOP + tid] = s_tval[tid];
    }
    if (tid < 32) {
        float s = s_tval[tid] + s_tval[tid + 32];
#pragma unroll
        for (int o = 16; o > 0; o >>= 1) s += __shfl_down_sync(0xffffffffu, s, o);
        if (tid == 0) g_row_sparse[row] = s;
    }
}

// ---------------- sparse decode + per-row squared residual ------------------
__global__ __launch_bounds__(128)
void decode_recon(const float* __restrict__ x)
{
    __shared__ int s_idx[K_TOP];
    __shared__ float s_val[K_TOP];
    __shared__ float s_red[128];
    const int tid = threadIdx.x;
    const int row = blockIdx.x;

    if (tid < K_TOP) {
        s_idx[tid] = g_top_idx[row * K_TOP + tid];
        s_val[tid] = g_top_val[row * K_TOP + tid];
    }
    __syncthreads();

    float4 acc = make_float4(0.f, 0.f, 0.f, 0.f);
#pragma unroll 8
    for (int j = 0; j < K_TOP; ++j) {
        const float v = s_val[j];
        const float4 d = ((const float4*)(g_decT + (size_t)s_idx[j] * H_DIM))[tid];
        acc.x += v * d.x; acc.y += v * d.y; acc.z += v * d.z; acc.w += v * d.w;
    }
    const float4 xs = ((const float4*)(x + (size_t)row * H_DIM))[tid];
    const float dx = acc.x - xs.x;
    const float dy = acc.y - xs.y;
    const float dz = acc.z - xs.z;
    const float dw = acc.w - xs.w;
    s_red[tid] = dx * dx + dy * dy + dz * dz + dw * dw;
    __syncthreads();
    for (int o = 64; o > 0; o >>= 1) {
        if (tid < o) s_red[tid] += s_red[tid + o];
        __syncthreads();
    }
    if (tid == 0) g_row_recon[row] = s_red[0];
}

// ---------------- final deterministic reduction ------------------------------
__global__ __launch_bounds__(1024)
void final_reduce(float* __restrict__ out)
{
    __shared__ float s_a[1024];
    __shared__ float s_b[1024];
    const int tid = threadIdx.x;
    float ra = 0.f, rb = 0.f;
#pragma unroll
    for (int i = 0; i < 8; ++i) {
        ra += g_row_recon[tid * 8 + i];
        rb += g_row_sparse[tid * 8 + i];
    }
    s_a[tid] = ra; s_b[tid] = rb;
    __syncthreads();
    for (int o = 512; o > 0; o >>= 1) {
        if (tid < o) { s_a[tid] += s_a[tid + o]; s_b[tid] += s_b[tid + o]; }
        __syncthreads();
    }
    if (tid == 0) {
        const float recon  = s_a[0] / (float)(N_ROWS * H_DIM);
        const float sparse = s_b[0] / (float)((size_t)N_ROWS * M_FEAT);
        out[0] = recon + 1e-3f * sparse;
    }
}

// ---------------- launch -----------------------------------------------------
extern "C" void kernel_launch(void* const* d_in, const int* in_sizes, int n_in,
                              void* d_out, int out_size)
{
    const float* zL       = (const float*)d_in[0];
    const float* enc      = (const float*)d_in[1];
    const float* dec      = (const float*)d_in[2];
    const float* bias_pre = (const float*)d_in[3];
    const float* bias_enc = (const float*)d_in[4];

    // idempotent, not a stream op, capture-safe; no static guard (rules)
    cudaFuncSetAttribute(gemm_mma, cudaFuncAttributeMaxDynamicSharedMemorySize, GEMM_SMEM);

    float* xr = nullptr; float* er = nullptr;
    cudaGetSymbolAddress((void**)&xr, g_xr);
    cudaGetSymbolAddress((void**)&er, g_er);

    round_tf32<<<(N_ROWS * H_DIM / 4) / 256, 256>>>(zL, xr);
    round_tf32<<<(M_FEAT * H_DIM / 4) / 256, 256>>>(enc, er);
    coff_kernel<<<M_FEAT / 8, 256>>>(enc, bias_pre, bias_enc);
    transpose_dec<<<dim3(M_FEAT / 32, H_DIM / 32), dim3(32, 8)>>>(dec);
    gemm_mma<<<dim3(M_FEAT / 128, N_ROWS / 128), 256, GEMM_SMEM>>>(xr, er);
    topk_kernel<<<N_ROWS, 256>>>();
    decode_recon<<<N_ROWS, 128>>>(zL);
    final_reduce<<<1, 1024>>>((float*)d_out);
}

// round 12
// speedup vs baseline: 4.5049x; 2.1623x over previous
#include <cuda_runtime.h>
#include <cuda_fp16.h>
#include <cstdint>

#define N_ROWS 8192
#define H_DIM  512
#define M_FEAT 4096
#define K_TOP  64

// GEMM tiling: CTA 128(rows) x 128(features), BK=64 halves (128B rows), 3-stage
#define BKH 64
#define NITER (H_DIM / BKH)             // 8
#define STAGES 3
#define STAGE_BYTES (2 * 128 * 128)     // A tile 16KB + B tile 16KB = 32KB
#define GEMM_SMEM (STAGES * STAGE_BYTES)

// ---------------- scratch (static device globals: allocation-free) ----------
__device__ __half g_logits_h[(size_t)N_ROWS * M_FEAT];  // 64 MB
__device__ __half g_decT_h[(size_t)M_FEAT * H_DIM];     // 4 MB
__device__ __half g_xh[(size_t)N_ROWS * H_DIM];         // 8 MB fp16 x
__device__ __half g_eh[(size_t)M_FEAT * H_DIM];         // 4 MB fp16 enc
__device__ float  g_coff[M_FEAT];                       // bias_enc - bias_pre@enc^T
__device__ int    g_top_idx[N_ROWS * K_TOP];
__device__ float  g_top_val[N_ROWS * K_TOP];
__device__ float  g_row_recon[N_ROWS];
__device__ float  g_row_sparse[N_ROWS];

// ---------------- PTX helpers (sm_80-era, portable to plain sm_103) ---------
__device__ __forceinline__ uint32_t smem_u32(const void* p) {
    uint32_t a;
    asm("{ .reg .u64 t; cvta.to.shared.u64 t, %1; cvt.u32.u64 %0, t; }" : "=r"(a) : "l"(p));
    return a;
}
#define CP_ASYNC16(dst, src) \
    asm volatile("cp.async.cg.shared.global [%0], [%1], 16;" :: "r"(dst), "l"(src))
#define CP_COMMIT() asm volatile("cp.async.commit_group;" ::: "memory")
#define CP_WAIT1()  asm volatile("cp.async.wait_group 1;" ::: "memory")

#define LDMATRIX_X4(r0, r1, r2, r3, a)                                     \
    asm volatile("ldmatrix.sync.aligned.m8n8.x4.shared.b16 {%0,%1,%2,%3}, [%4];" \
        : "=r"(r0), "=r"(r1), "=r"(r2), "=r"(r3) : "r"(a))

#define MMA_F16(d, a, b0, b1)                                              \
    asm volatile("mma.sync.aligned.m16n8k16.row.col.f32.f16.f16.f32 "      \
        "{%0,%1,%2,%3}, {%4,%5,%6,%7}, {%8,%9}, {%0,%1,%2,%3};"            \
        : "+f"((d)[0]), "+f"((d)[1]), "+f"((d)[2]), "+f"((d)[3])           \
        : "r"((a)[0]), "r"((a)[1]), "r"((a)[2]), "r"((a)[3]),              \
          "r"(b0), "r"(b1))

// ---------------- preprocessing: f32 -> f16 ----------------------------------
__global__ void to_half(const float* __restrict__ in, __half* __restrict__ out)
{
    const int i = blockIdx.x * blockDim.x + threadIdx.x;
    const float4 v = ((const float4*)in)[i];
    __half2 h0 = __floats2half2_rn(v.x, v.y);
    __half2 h1 = __floats2half2_rn(v.z, v.w);
    ((__half2*)out)[i * 2]     = h0;
    ((__half2*)out)[i * 2 + 1] = h1;
}

__global__ void coff_kernel(const float* __restrict__ enc,
                            const float* __restrict__ bias_pre,
                            const float* __restrict__ bias_enc)
{
    const int wid = threadIdx.x >> 5, lane = threadIdx.x & 31;
    const int f = blockIdx.x * 8 + wid;
    float s = 0.f;
#pragma unroll
    for (int i = 0; i < 16; ++i) {
        const int k = lane + i * 32;
        s = fmaf(enc[(size_t)f * H_DIM + k], bias_pre[k], s);
    }
#pragma unroll
    for (int o = 16; o > 0; o >>= 1) s += __shfl_down_sync(0xffffffffu, s, o);
    if (lane == 0) g_coff[f] = bias_enc[f] - s;
}

// ---------------- transpose dec [H, M] -> decT_h [M, H] (fp16) --------------
__global__ void transpose_dec(const float* __restrict__ dec)
{
    __shared__ float t[32][33];
    const int bx = blockIdx.x, by = blockIdx.y;
    const int tx = threadIdx.x, ty = threadIdx.y;
#pragma unroll
    for (int j = 0; j < 4; ++j)
        t[ty + j * 8][tx] = dec[(size_t)(by * 32 + ty + j * 8) * M_FEAT + bx * 32 + tx];
    __syncthreads();
#pragma unroll
    for (int j = 0; j < 4; ++j)
        g_decT_h[(size_t)(bx * 32 + ty + j * 8) * H_DIM + by * 32 + tx] =
            __float2half_rn(t[tx][ty + j * 8]);
}

// ---------------- fp16 mma.sync GEMM + bias + relu --------------------------
// logits[i, j] = relu(sum_k xh[i,k]*eh[j,k] + coff[j]), stored fp16
// NT GEMM: both operands K-major, 128B rows, XOR-8 swizzle, ldmatrix loads.
__global__ __launch_bounds__(256)
void gemm_mma(const __half* __restrict__ xh, const __half* __restrict__ eh)
{
    extern __shared__ __align__(1024) char smem[];
    const uint32_t smem_b = smem_u32(smem);
    const int tid = threadIdx.x;
    const int lane = tid & 31, warp = tid >> 5;
    const int warp_m = warp & 1;        // 2 warps along rows -> 64 rows each
    const int warp_n = warp >> 1;       // 4 warps along features -> 32 each
    const int nBase = blockIdx.y * 128; // sample rows
    const int mBase = blockIdx.x * 128; // features

    // ---- cp.async per-thread slots: 128 rows x 8 x 16B chunks per operand ----
    uint32_t offq[4];
    const __half* pA[4];
    const __half* pB[4];
#pragma unroll
    for (int q = 0; q < 4; ++q) {
        const int v = tid + q * 256;          // 0..1023
        const int row = v >> 3, c = v & 7;
        offq[q] = (uint32_t)(row * 128 + ((c ^ (row & 7)) << 4));
        pA[q] = xh + (size_t)(nBase + row) * H_DIM + c * 8;
        pB[q] = eh + (size_t)(mBase + row) * H_DIM + c * 8;
    }

    // ---- ldmatrix per-lane address constants ----
    const int qd = lane >> 3, r = lane & 7;
    // A fragment matrices: [m+0 kLo][m+8 kLo][m+0 kHi][m+8 kHi]
    const int rowA = warp_m * 64 + ((qd & 1) << 3) + r;
    const int qhA = qd >> 1;
    const uint32_t baseA = (uint32_t)(rowA * 128);
    const int swA = rowA & 7;
    // B fragment matrices: [n+0 kLo][n+0 kHi][n+8 kLo][n+8 kHi]
    const int rowB = warp_n * 32 + ((qd >> 1) << 3) + r;
    const int qbB = qd & 1;
    const uint32_t baseB = (uint32_t)(128 * 128 + rowB * 128);
    const int swB = rowB & 7;

    float acc[4][4][4];
#pragma unroll
    for (int mt = 0; mt < 4; ++mt)
#pragma unroll
        for (int nt = 0; nt < 4; ++nt)
#pragma unroll
            for (int e = 0; e < 4; ++e) acc[mt][nt][e] = 0.f;

    // ---- prologue: stages for iters 0,1 ----
#pragma unroll
    for (int i = 0; i < 2; ++i) {
        const uint32_t st = smem_b + i * STAGE_BYTES;
        const int k0 = i * BKH;
#pragma unroll
        for (int q = 0; q < 4; ++q) {
            CP_ASYNC16(st + offq[q], pA[q] + k0);
            CP_ASYNC16(st + 128 * 128 + offq[q], pB[q] + k0);
        }
        CP_COMMIT();
    }

#pragma unroll 1
    for (int i = 0; i < NITER; ++i) {
        CP_WAIT1();                 // chunk i landed (newest group may lag)
        __syncthreads();            // publish chunk i; stage (i+2)%3 free

        const int il = i + 2;
        if (il < NITER) {
            const uint32_t st = smem_b + (il % STAGES) * STAGE_BYTES;
            const int k0 = il * BKH;
#pragma unroll
            for (int q = 0; q < 4; ++q) {
                CP_ASYNC16(st + offq[q], pA[q] + k0);
                CP_ASYNC16(st + 128 * 128 + offq[q], pB[q] + k0);
            }
        }
        CP_COMMIT();

        const uint32_t st = smem_b + (i % STAGES) * STAGE_BYTES;
#pragma unroll
        for (int ks = 0; ks < 4; ++ks) {       // 4 x K=16 per 128B row
            uint32_t a[4][4];
#pragma unroll
            for (int mt = 0; mt < 4; ++mt) {
                const uint32_t ad = st + baseA + mt * 2048
                                  + (uint32_t)((((ks * 2) | qhA) ^ swA) << 4);
                LDMATRIX_X4(a[mt][0], a[mt][1], a[mt][2], a[mt][3], ad);
            }
            uint32_t b[2][4];
#pragma unroll
            for (int p = 0; p < 2; ++p) {
                const uint32_t bd = st + baseB + p * 2048
                                  + (uint32_t)((((ks * 2) | qbB) ^ swB) << 4);
                LDMATRIX_X4(b[p][0], b[p][1], b[p][2], b[p][3], bd);
            }
#pragma unroll
            for (int mt = 0; mt < 4; ++mt)
#pragma unroll
                for (int nt = 0; nt < 4; ++nt)
                    MMA_F16(acc[mt][nt], a[mt],
                            b[nt >> 1][(nt & 1) * 2], b[nt >> 1][(nt & 1) * 2 + 1]);
        }
    }

    // ---- epilogue: + coff, relu, fp16 store ----
#pragma unroll
    for (int mt = 0; mt < 4; ++mt) {
#pragma unroll
        for (int nt = 0; nt < 4; ++nt) {
            const int row0 = nBase + warp_m * 64 + mt * 16 + (lane >> 2);
            const int col  = mBase + warp_n * 32 + nt * 8 + (lane & 3) * 2;
            const float2 cb = *(const float2*)(g_coff + col);
            const __half2 o0 = __floats2half2_rn(fmaxf(acc[mt][nt][0] + cb.x, 0.f),
                                                 fmaxf(acc[mt][nt][1] + cb.y, 0.f));
            const __half2 o1 = __floats2half2_rn(fmaxf(acc[mt][nt][2] + cb.x, 0.f),
                                                 fmaxf(acc[mt][nt][3] + cb.y, 0.f));
            *(__half2*)(g_logits_h + (size_t)row0 * M_FEAT + col)       = o0;
            *(__half2*)(g_logits_h + (size_t)(row0 + 8) * M_FEAT + col) = o1;
        }
    }
}

// ---------------- exact per-row top-64, 2-pass radix on fp16 bits ------------
// relu'd values >= 0, so fp16 bit pattern is monotonic as unsigned 16-bit.
__global__ __launch_bounds__(256)
void topk_kernel()
{
    __shared__ __align__(16) __half s_row[M_FEAT];
    __shared__ int s_hist[256];
    __shared__ int s_wsum[8];
    __shared__ int s_tidx[K_TOP];
    __shared__ float s_tval[K_TOP];
    __shared__ unsigned s_prefix;
    __shared__ int s_krem;

    const int tid = threadIdx.x;
    const int lane = tid & 31, wid = tid >> 5;
    const int row = blockIdx.x;
    const float4* src = (const float4*)(g_logits_h + (size_t)row * M_FEAT);
    ((float4*)s_row)[tid]       = src[tid];
    ((float4*)s_row)[tid + 256] = src[tid + 256];
    if (tid == 0) { s_prefix = 0u; s_krem = K_TOP; }
    __syncthreads();

    const int base = tid * 16;

#pragma unroll 1
    for (int p = 1; p >= 0; --p) {
        const unsigned pref = s_prefix;
        const int krem = s_krem;
        s_hist[tid] = 0;
        __syncthreads();
        const unsigned pmask = (p == 1) ? 0u : 0xFF00u;
        const int shift = p * 8;
#pragma unroll
        for (int i = 0; i < 16; ++i) {
            const unsigned b = (unsigned)__half_as_ushort(s_row[base + i]);
            if ((b & pmask) == pref) atomicAdd(&s_hist[(b >> shift) & 255], 1);
        }
        __syncthreads();
        // parallel suffix count over bins: thread handles bin = 255 - tid
        const int bin = 255 - tid;
        const int h = s_hist[bin];
        int x = h;
#pragma unroll
        for (int o = 1; o < 32; o <<= 1) {
            int y = __shfl_up_sync(0xffffffffu, x, o);
            if (lane >= o) x += y;
        }
        if (lane == 31) s_wsum[wid] = x;
        __syncthreads();
        int off = 0;
#pragma unroll
        for (int w = 0; w < 8; ++w) off += (w < wid) ? s_wsum[w] : 0;
        const int cnt_ge = x + off;     // values with byte-bin >= bin
        if (cnt_ge >= krem && (cnt_ge - h) < krem) {   // exactly one thread
            s_prefix = pref | ((unsigned)bin << shift);
            s_krem = krem - (cnt_ge - h);
        }
        __syncthreads();
    }

    const unsigned T = s_prefix;

    int c_gt = 0, c_eq = 0;
#pragma unroll
    for (int i = 0; i < 16; ++i) {
        const unsigned b = (unsigned)__half_as_ushort(s_row[base + i]);
        c_gt += (b > T);
        c_eq += (b == T);
    }
    const int packed = c_gt | (c_eq << 16);
    int x = packed;
#pragma unroll
    for (int o = 1; o < 32; o <<= 1) {
        int y = __shfl_up_sync(0xffffffffu, x, o);
        if (lane >= o) x += y;
    }
    if (lane == 31) s_wsum[wid] = x;
    __syncthreads();
    int off = 0, tot = 0;
#pragma unroll
    for (int w = 0; w < 8; ++w) {
        const int v = s_wsum[w];
        if (w < wid) off += v;
        tot += v;
    }
    const int incl = x + off;
    const int excl = incl - packed;
    const int tot_gt = tot & 0xffff;
    int p_gt = excl & 0xffff;
    int p_eq = tot_gt + (excl >> 16);

#pragma unroll
    for (int i = 0; i < 16; ++i) {
        const __half hv = s_row[base + i];
        const unsigned b = (unsigned)__half_as_ushort(hv);
        if (b > T) {
            s_tidx[p_gt] = base + i; s_tval[p_gt] = __half2float(hv); ++p_gt;
        } else if (b == T && p_eq < K_TOP) {
            s_tidx[p_eq] = base + i; s_tval[p_eq] = __half2float(hv); ++p_eq;
        }
    }
    __syncthreads();

    if (tid < K_TOP) {
        g_top_idx[row * K_TOP + tid] = s_tidx[tid];
        g_top_val[row * K_TOP + tid] = s_tval[tid];
    }
    if (tid < 32) {
        float s = s_tval[tid] + s_tval[tid + 32];
#pragma unroll
        for (int o = 16; o > 0; o >>= 1) s += __shfl_down_sync(0xffffffffu, s, o);
        if (tid == 0) g_row_sparse[row] = s;
    }
}

// ---------------- sparse decode (fp16 dict) + per-row squared residual ------
__global__ __launch_bounds__(128)
void decode_recon(const float* __restrict__ x)
{
    __shared__ int s_idx[K_TOP];
    __shared__ float s_val[K_TOP];
    __shared__ float s_red[128];
    const int tid = threadIdx.x;
    const int row = blockIdx.x;

    if (tid < K_TOP) {
        s_idx[tid] = g_top_idx[row * K_TOP + tid];
        s_val[tid] = g_top_val[row * K_TOP + tid];
    }
    __syncthreads();

    float4 acc = make_float4(0.f, 0.f, 0.f, 0.f);
#pragma unroll 8
    for (int j = 0; j < K_TOP; ++j) {
        const float v = s_val[j];
        const uint2 u = ((const uint2*)(g_decT_h + (size_t)s_idx[j] * H_DIM))[tid];
        const float2 d01 = __half22float2(*(const __half2*)&u.x);
        const float2 d23 = __half22float2(*(const __half2*)&u.y);
        acc.x += v * d01.x; acc.y += v * d01.y;
        acc.z += v * d23.x; acc.w += v * d23.y;
    }
    const float4 xs = ((const float4*)(x + (size_t)row * H_DIM))[tid];
    const float dx = acc.x - xs.x;
    const float dy = acc.y - xs.y;
    const float dz = acc.z - xs.z;
    const float dw = acc.w - xs.w;
    s_red[tid] = dx * dx + dy * dy + dz * dz + dw * dw;
    __syncthreads();
    for (int o = 64; o > 0; o >>= 1) {
        if (tid < o) s_red[tid] += s_red[tid + o];
        __syncthreads();
    }
    if (tid == 0) g_row_recon[row] = s_red[0];
}

// ---------------- final deterministic reduction ------------------------------
__global__ __launch_bounds__(1024)
void final_reduce(float* __restrict__ out)
{
    __shared__ float s_a[1024];
    __shared__ float s_b[1024];
    const int tid = threadIdx.x;
    float ra = 0.f, rb = 0.f;
#pragma unroll
    for (int i = 0; i < 8; ++i) {
        ra += g_row_recon[tid * 8 + i];
        rb += g_row_sparse[tid * 8 + i];
    }
    s_a[tid] = ra; s_b[tid] = rb;
    __syncthreads();
    for (int o = 512; o > 0; o >>= 1) {
        if (tid < o) { s_a[tid] += s_a[tid + o]; s_b[tid] += s_b[tid + o]; }
        __syncthreads();
    }
    if (tid == 0) {
        const float recon  = s_a[0] / (float)(N_ROWS * H_DIM);
        const float sparse = s_b[0] / (float)((size_t)N_ROWS * M_FEAT);
        out[0] = recon + 1e-3f * sparse;
    }
}

// ---------------- launch -----------------------------------------------------
extern "C" void kernel_launch(void* const* d_in, const int* in_sizes, int n_in,
                              void* d_out, int out_size)
{
    const float* zL       = (const float*)d_in[0];
    const float* enc      = (const float*)d_in[1];
    const float* dec      = (const float*)d_in[2];
    const float* bias_pre = (const float*)d_in[3];
    const float* bias_enc = (const float*)d_in[4];

    cudaFuncSetAttribute(gemm_mma, cudaFuncAttributeMaxDynamicSharedMemorySize, GEMM_SMEM);

    __half* xh = nullptr; __half* eh = nullptr;
    cudaGetSymbolAddress((void**)&xh, g_xh);
    cudaGetSymbolAddress((void**)&eh, g_eh);

    to_half<<<(N_ROWS * H_DIM / 4) / 256, 256>>>(zL, xh);
    to_half<<<(M_FEAT * H_DIM / 4) / 256, 256>>>(enc, eh);
    coff_kernel<<<M_FEAT / 8, 256>>>(enc, bias_pre, bias_enc);
    transpose_dec<<<dim3(M_FEAT / 32, H_DIM / 32), dim3(32, 8)>>>(dec);
    gemm_mma<<<dim3(M_FEAT / 128, N_ROWS / 128), 256, GEMM_SMEM>>>(xh, eh);
    topk_kernel<<<N_ROWS, 256>>>();
    decode_recon<<<N_ROWS, 128>>>(zL);
    final_reduce<<<1, 1024>>>((float*)d_out);
}